// round 11
// baseline (speedup 1.0000x reference)
#include <cuda_runtime.h>
#include <cuda_bf16.h>
#include <math.h>
#include <stdint.h>

// Problem constants
#define BATCH 2
#define SEQ   2048
#define DMODEL 2048
#define NHEADS 16
#define DHEAD 128
#define MROWS (BATCH*SEQ)        // 4096
#define NQKV  (3*DMODEL)         // 6144

// ---------------------------------------------------------------------------
// Scratch (device globals; no runtime allocation allowed). bf16 hi/lo planes.
// ---------------------------------------------------------------------------
__device__ float g_q [ (size_t)MROWS * DMODEL ];                  // q pre-norm fp32
__device__ __nv_bfloat16 g_xh [ (size_t)MROWS * DMODEL ];
__device__ __nv_bfloat16 g_xl [ (size_t)MROWS * DMODEL ];
__device__ __nv_bfloat16 g_Wqh[ (size_t)NQKV  * DMODEL ];
__device__ __nv_bfloat16 g_Wql[ (size_t)NQKV  * DMODEL ];
__device__ __nv_bfloat16 g_Woh[ (size_t)DMODEL* DMODEL ];
__device__ __nv_bfloat16 g_Wol[ (size_t)DMODEL* DMODEL ];
__device__ __nv_bfloat16 g_qh [ (size_t)MROWS * DMODEL ];
__device__ __nv_bfloat16 g_ql [ (size_t)MROWS * DMODEL ];
__device__ __nv_bfloat16 g_kh [ (size_t)MROWS * DMODEL ];
__device__ __nv_bfloat16 g_kl [ (size_t)MROWS * DMODEL ];
__device__ __nv_bfloat16 g_vh [ (size_t)MROWS * DMODEL ];
__device__ __nv_bfloat16 g_vl [ (size_t)MROWS * DMODEL ];
__device__ __nv_bfloat16 g_zh [ (size_t)MROWS * DMODEL ];
__device__ __nv_bfloat16 g_zl [ (size_t)MROWS * DMODEL ];

// ---------------------------------------------------------------------------
// helpers
// ---------------------------------------------------------------------------
__device__ __forceinline__ uint32_t smem_u32(const void* p) {
    return (uint32_t)__cvta_generic_to_shared(p);
}
__device__ __forceinline__ void cp16(void* dst, const void* src) {
    asm volatile("cp.async.cg.shared.global [%0], [%1], 16;"
                 :: "r"(smem_u32(dst)), "l"(src));
}
__device__ __forceinline__ void cp_commit() { asm volatile("cp.async.commit_group;"); }
template<int N> __device__ __forceinline__ void cp_wait() {
    asm volatile("cp.async.wait_group %0;" :: "n"(N));
}
__device__ __forceinline__ void ldsm_x4(uint32_t addr, uint32_t& r0, uint32_t& r1,
                                        uint32_t& r2, uint32_t& r3) {
    asm volatile("ldmatrix.sync.aligned.m8n8.x4.shared.b16 {%0,%1,%2,%3}, [%4];"
                 : "=r"(r0), "=r"(r1), "=r"(r2), "=r"(r3) : "r"(addr));
}
__device__ __forceinline__ void ldsm_x4_t(uint32_t addr, uint32_t& r0, uint32_t& r1,
                                          uint32_t& r2, uint32_t& r3) {
    asm volatile("ldmatrix.sync.aligned.m8n8.x4.trans.shared.b16 {%0,%1,%2,%3}, [%4];"
                 : "=r"(r0), "=r"(r1), "=r"(r2), "=r"(r3) : "r"(addr));
}
__device__ __forceinline__ void mma16816(float* d, const uint32_t* a, const uint32_t* b) {
    asm volatile(
        "mma.sync.aligned.m16n8k16.row.col.f32.bf16.bf16.f32 "
        "{%0,%1,%2,%3}, {%4,%5,%6,%7}, {%8,%9}, {%0,%1,%2,%3};"
        : "+f"(d[0]), "+f"(d[1]), "+f"(d[2]), "+f"(d[3])
        : "r"(a[0]), "r"(a[1]), "r"(a[2]), "r"(a[3]), "r"(b[0]), "r"(b[1]));
}

// ---------------------------------------------------------------------------
// fp32 -> bf16 hi/lo plane split
// ---------------------------------------------------------------------------
__global__ void split_kernel(const float* __restrict__ in,
                             __nv_bfloat16* __restrict__ h,
                             __nv_bfloat16* __restrict__ l, int n4)
{
    int i = blockIdx.x * blockDim.x + threadIdx.x;
    if (i >= n4) return;
    float4 v = ((const float4*)in)[i];
    __nv_bfloat162 h0 = __floats2bfloat162_rn(v.x, v.y);
    __nv_bfloat162 h1 = __floats2bfloat162_rn(v.z, v.w);
    float2 f0 = __bfloat1622float2(h0);
    float2 f1 = __bfloat1622float2(h1);
    __nv_bfloat162 l0 = __floats2bfloat162_rn(v.x - f0.x, v.y - f0.y);
    __nv_bfloat162 l1 = __floats2bfloat162_rn(v.z - f1.x, v.w - f1.y);
    ((__nv_bfloat162*)h)[2*i]   = h0;
    ((__nv_bfloat162*)h)[2*i+1] = h1;
    ((__nv_bfloat162*)l)[2*i]   = l0;
    ((__nv_bfloat162*)l)[2*i+1] = l1;
}

// ---------------------------------------------------------------------------
// bf16x3 GEMM from planes, 2-stage cp.async pipeline, 2 CTAs/SM. (unchanged R10)
// ---------------------------------------------------------------------------
#define GP 40
#define GSTAGES 2
#define GTSZ (128 * GP)

__global__ __launch_bounds__(256, 2)
void gemm_planes(const __nv_bfloat16* __restrict__ Ah, const __nv_bfloat16* __restrict__ Al,
                 const __nv_bfloat16* __restrict__ Bh, const __nv_bfloat16* __restrict__ Bl,
                 const float* __restrict__ bias,
                 float* __restrict__ C0, float* __restrict__ C1, float* __restrict__ C2,
                 __nv_bfloat16* __restrict__ VH, __nv_bfloat16* __restrict__ VL,
                 int M, int N, int K, int mode)
{
    extern __shared__ __nv_bfloat16 smg[];
    __nv_bfloat16* sAh = smg;
    __nv_bfloat16* sAl = sAh + GSTAGES * GTSZ;
    __nv_bfloat16* sBh = sAl + GSTAGES * GTSZ;
    __nv_bfloat16* sBl = sBh + GSTAGES * GTSZ;

    const int tid  = threadIdx.x;
    const int wid  = tid >> 5;
    const int lane = tid & 31;
    const int wm   = wid >> 2;
    const int wn   = wid & 3;
    const int m0   = blockIdx.y * 128;
    const int n0   = blockIdx.x * 128;

    const int lrow = tid >> 1;
    const int lcol = (tid & 1) * 16;

    float acc[4][4][4];
#pragma unroll
    for (int i = 0; i < 4; i++)
#pragma unroll
        for (int j = 0; j < 4; j++)
#pragma unroll
            for (int r = 0; r < 4; r++) acc[i][j][r] = 0.f;

    const int iters = K / 32;

    auto load_tile = [&](int t, int st) {
        size_t ga = (size_t)(m0 + lrow) * K + t * 32 + lcol;
        size_t gb = (size_t)(n0 + lrow) * K + t * 32 + lcol;
        size_t so = (size_t)st * GTSZ + lrow * GP + lcol;
        cp16(sAh + so,     Ah + ga);
        cp16(sAh + so + 8, Ah + ga + 8);
        cp16(sAl + so,     Al + ga);
        cp16(sAl + so + 8, Al + ga + 8);
        cp16(sBh + so,     Bh + gb);
        cp16(sBh + so + 8, Bh + gb + 8);
        cp16(sBl + so,     Bl + gb);
        cp16(sBl + so + 8, Bl + gb + 8);
    };

    load_tile(0, 0); cp_commit();

    for (int it = 0; it < iters; ++it) {
        __syncthreads();
        if (it + 1 < iters) { load_tile(it + 1, (it + 1) & 1); cp_commit(); cp_wait<1>(); }
        else cp_wait<0>();
        __syncthreads();

        const __nv_bfloat16* tAh = sAh + (size_t)(it & 1) * GTSZ;
        const __nv_bfloat16* tAl = sAl + (size_t)(it & 1) * GTSZ;
        const __nv_bfloat16* tBh = sBh + (size_t)(it & 1) * GTSZ;
        const __nv_bfloat16* tBl = sBl + (size_t)(it & 1) * GTSZ;

#pragma unroll
        for (int ks = 0; ks < 2; ks++) {
            const int kk = ks * 16;
            uint32_t afh[4][4], afl[4][4];
#pragma unroll
            for (int mt = 0; mt < 4; mt++) {
                int r = wm * 64 + mt * 16 + (lane & 15);
                int c = kk + ((lane >> 4) * 8);
                ldsm_x4(smem_u32(tAh + r * GP + c), afh[mt][0], afh[mt][1], afh[mt][2], afh[mt][3]);
                ldsm_x4(smem_u32(tAl + r * GP + c), afl[mt][0], afl[mt][1], afl[mt][2], afl[mt][3]);
            }
            uint32_t bfh[4][2], bfl[4][2];
#pragma unroll
            for (int p = 0; p < 2; p++) {
                int r = wn * 32 + p * 16 + (lane & 15);
                int c = kk + ((lane >> 4) * 8);
                uint32_t t0, t1, t2, t3;
                ldsm_x4(smem_u32(tBh + r * GP + c), t0, t1, t2, t3);
                bfh[2*p][0] = t0; bfh[2*p][1] = t2;
                bfh[2*p+1][0] = t1; bfh[2*p+1][1] = t3;
                ldsm_x4(smem_u32(tBl + r * GP + c), t0, t1, t2, t3);
                bfl[2*p][0] = t0; bfl[2*p][1] = t2;
                bfl[2*p+1][0] = t1; bfl[2*p+1][1] = t3;
            }
#pragma unroll
            for (int mt = 0; mt < 4; mt++)
#pragma unroll
                for (int nt = 0; nt < 4; nt++) {
                    mma16816(acc[mt][nt], afh[mt], bfh[nt]);
                    mma16816(acc[mt][nt], afh[mt], bfl[nt]);
                    mma16816(acc[mt][nt], afl[mt], bfh[nt]);
                }
        }
    }

#pragma unroll
    for (int mt = 0; mt < 4; mt++)
#pragma unroll
        for (int nt = 0; nt < 4; nt++)
#pragma unroll
            for (int r = 0; r < 4; r++) {
                size_t row = m0 + wm * 64 + mt * 16 + (lane >> 2) + (r >> 1) * 8;
                int    col = n0 + wn * 32 + nt * 8 + (lane & 3) * 2 + (r & 1);
                float v = acc[mt][nt][r] + bias[col];
                if (mode == 0) {
                    C0[row * (size_t)N + col] = v;
                } else {
                    if (col < DMODEL) {
                        C0[row * (size_t)DMODEL + col] = v;
                    } else if (col < 2 * DMODEL) {
                        C1[row * (size_t)DMODEL + (col - DMODEL)] = v;
                    } else {
                        size_t idx = row * (size_t)DMODEL + (col - 2 * DMODEL);
                        C2[idx] = v;
                        __nv_bfloat16 hh = __float2bfloat16(v);
                        VH[idx] = hh;
                        VL[idx] = __float2bfloat16(v - __bfloat162float(hh));
                    }
                }
            }
}

// ---------------------------------------------------------------------------
// RMS norm per head (128 elems) -> bf16 hi/lo planes.
// ---------------------------------------------------------------------------
__global__ void rmsnorm_split(const float* __restrict__ qin, const float* __restrict__ kin,
                              __nv_bfloat16* __restrict__ qh, __nv_bfloat16* __restrict__ ql,
                              __nv_bfloat16* __restrict__ kh, __nv_bfloat16* __restrict__ kl,
                              const float* __restrict__ wq, const float* __restrict__ wk)
{
    const float* in;  __nv_bfloat16 *oh, *ol;  const float* w;
    if (blockIdx.y == 0) { in = qin; oh = qh; ol = ql; w = wq; }
    else                 { in = kin; oh = kh; ol = kl; w = wk; }

    size_t base = (size_t)blockIdx.x * DHEAD;
    int t = threadIdx.x;
    float v = in[base + t];
    float ss = v * v;
#pragma unroll
    for (int o = 16; o > 0; o >>= 1) ss += __shfl_xor_sync(0xffffffffu, ss, o);

    __shared__ float sred[4];
    int wrp = t >> 5, lane = t & 31;
    if (lane == 0) sred[wrp] = ss;
    __syncthreads();
    float tot = sred[0] + sred[1] + sred[2] + sred[3];
    float inv = rsqrtf(tot * (1.0f / DHEAD) + 1e-6f);
    float vn = v * inv * w[t];
    __nv_bfloat16 hh = __float2bfloat16(vn);
    oh[base + t] = hh;
    ol[base + t] = __float2bfloat16(vn - __bfloat162float(hh));
}

// ---------------------------------------------------------------------------
// Fused flash attention, NO-RESCALE softmax (p = exp(s-44); |s|<=128 so safe),
// 256 threads = 8 warps (4 row-groups x 2 key/dh-halves), 2 CTAs/SM.
// Q tile 64 rows (swizzled, no pad). K/V 32-key tiles double-buffered.
// Warp (g,d): S for rows g*16.. x keys d*16..(16); PV for rows x dh d*64..(64).
// P crosses warps via smem staging (pitch 40, GEMM-A ldsm pattern).
// grid = (SEQ/64, NHEADS, BATCH)
// ---------------------------------------------------------------------------
#define KVP 136
#define KVT (32 * KVP)
#define PP  40
#define SHIFT_C 44.0f

// Q swizzle: 256B rows, 16B chunk index XOR (row&7) -> conflict-free ldsm
__device__ __forceinline__ uint32_t qswiz(int row, int chunk) {
    return (uint32_t)(row * 256 + ((chunk ^ (row & 7)) << 4));
}

__global__ __launch_bounds__(256, 2)
void attn_tc4(const __nv_bfloat16* __restrict__ Qh_g, const __nv_bfloat16* __restrict__ Ql_g,
              const __nv_bfloat16* __restrict__ Kh_g, const __nv_bfloat16* __restrict__ Kl_g,
              const __nv_bfloat16* __restrict__ Vh_g, const __nv_bfloat16* __restrict__ Vl_g,
              __nv_bfloat16* __restrict__ ZH, __nv_bfloat16* __restrict__ ZL)
{
    extern __shared__ __nv_bfloat16 smx[];
    __nv_bfloat16* Qh = smx;                 // 64 rows x 128 (swizzled)
    __nv_bfloat16* Ql = Qh + 64 * 128;
    __nv_bfloat16* Kh = Ql + 64 * 128;       // 2 stages x 32 x KVP
    __nv_bfloat16* Kl = Kh + 2 * KVT;
    __nv_bfloat16* Vh = Kl + 2 * KVT;
    __nv_bfloat16* Vl = Vh + 2 * KVT;
    __nv_bfloat16* Ph = Vl + 2 * KVT;        // 64 x PP
    __nv_bfloat16* Pl = Ph + 64 * PP;

    const int tid  = threadIdx.x;
    const int wid  = tid >> 5;
    const int lane = tid & 31;
    const int g    = wid & 3;                // row group (16 rows)
    const int d    = wid >> 2;               // key-half (S) / dh-half (PV)
    const int b  = blockIdx.z;
    const int h  = blockIdx.y;
    const int q0 = blockIdx.x * 64;
    const size_t rowBase = (size_t)b * SEQ;
    const int colBase = h * DHEAD;

    // ---- Q tile load (swizzled): 64 rows x 16 chunks of 16B per plane
#pragma unroll
    for (int i = 0; i < 4; i++) {
        int c = i * 256 + tid;               // 0..1023
        int r = c >> 4, ch = c & 15;
        size_t gptr = (rowBase + q0 + r) * DMODEL + colBase + ch * 8;
        *(uint4*)((char*)Qh + qswiz(r, ch)) = *(const uint4*)(Qh_g + gptr);
        *(uint4*)((char*)Ql + qswiz(r, ch)) = *(const uint4*)(Ql_g + gptr);
    }

    auto load_tile = [&](int jt, int st) {
        int kr0 = jt * 32;
#pragma unroll
        for (int i = 0; i < 2; i++) {
            int c = i * 256 + tid;           // 0..511
            int r = c >> 4, col = (c & 15) * 8;
            size_t gptr = (rowBase + kr0 + r) * DMODEL + colBase + col;
            size_t s = (size_t)st * KVT + r * KVP + col;
            cp16(Kh + s, Kh_g + gptr);
            cp16(Kl + s, Kl_g + gptr);
            cp16(Vh + s, Vh_g + gptr);
            cp16(Vl + s, Vl_g + gptr);
        }
    };

    float o[8][4];
#pragma unroll
    for (int i = 0; i < 8; i++)
#pragma unroll
        for (int r = 0; r < 4; r++) o[i][r] = 0.f;
    float lp[2] = {0.f, 0.f};                // per-lane partial row sums

    load_tile(0, 0); cp_commit();

    const int NT = SEQ / 32;                 // 64 tiles
    for (int jt = 0; jt < NT; jt++) {
        __syncthreads();                     // WAR: KV buffer + P stage free
        if (jt + 1 < NT) { load_tile(jt + 1, (jt + 1) & 1); cp_commit(); cp_wait<1>(); }
        else cp_wait<0>();
        __syncthreads();                     // tile jt visible (and Q on jt=0)

        const size_t st = (size_t)(jt & 1) * KVT;

        // ---- S = Q K^T : warp rows [g*16,+16) x keys [d*16,+16)
        float s[2][4];
#pragma unroll
        for (int i = 0; i < 2; i++)
#pragma unroll
            for (int r = 0; r < 4; r++) s[i][r] = 0.f;

#pragma unroll
        for (int ks = 0; ks < 8; ks++) {
            uint32_t ah[4], al[4];
            {
                int r = g * 16 + (lane & 15);
                int ch = ks * 2 + (lane >> 4);
                ldsm_x4(smem_u32((char*)Qh + qswiz(r, ch)), ah[0], ah[1], ah[2], ah[3]);
                ldsm_x4(smem_u32((char*)Ql + qswiz(r, ch)), al[0], al[1], al[2], al[3]);
            }
            int r = d * 16 + (lane & 15);
            int c = ks * 16 + ((lane >> 4) * 8);
            uint32_t t0, t1, t2, t3;
            uint32_t bh0[2], bh1[2], bl0[2], bl1[2];
            ldsm_x4(smem_u32(Kh + st + r * KVP + c), t0, t1, t2, t3);
            bh0[0] = t0; bh0[1] = t2; bh1[0] = t1; bh1[1] = t3;
            ldsm_x4(smem_u32(Kl + st + r * KVP + c), t0, t1, t2, t3);
            bl0[0] = t0; bl0[1] = t2; bl1[0] = t1; bl1[1] = t3;
            mma16816(s[0], ah, bh0);
            mma16816(s[0], ah, bl0);
            mma16816(s[0], al, bh0);
            mma16816(s[1], ah, bh1);
            mma16816(s[1], ah, bl1);
            mma16816(s[1], al, bh1);
        }

        // ---- p = exp(s - 44), accumulate partial l, stage P to smem
#pragma unroll
        for (int nt = 0; nt < 2; nt++) {
            float p0 = __expf(s[nt][0] - SHIFT_C);
            float p1 = __expf(s[nt][1] - SHIFT_C);
            float p2 = __expf(s[nt][2] - SHIFT_C);
            float p3 = __expf(s[nt][3] - SHIFT_C);
            lp[0] += p0 + p1;
            lp[1] += p2 + p3;
            int colp = d * 16 + nt * 8 + (lane & 3) * 2;
            int r0 = g * 16 + (lane >> 2);
            __nv_bfloat162 hh0 = __floats2bfloat162_rn(p0, p1);
            float2 f0 = __bfloat1622float2(hh0);
            __nv_bfloat162 ll0 = __floats2bfloat162_rn(p0 - f0.x, p1 - f0.y);
            *(__nv_bfloat162*)(Ph + r0 * PP + colp) = hh0;
            *(__nv_bfloat162*)(Pl + r0 * PP + colp) = ll0;
            __nv_bfloat162 hh1 = __floats2bfloat162_rn(p2, p3);
            float2 f1 = __bfloat1622float2(hh1);
            __nv_bfloat162 ll1 = __floats2bfloat162_rn(p2 - f1.x, p3 - f1.y);
            *(__nv_bfloat162*)(Ph + (r0 + 8) * PP + colp) = hh1;
            *(__nv_bfloat162*)(Pl + (r0 + 8) * PP + colp) = ll1;
        }
        __syncthreads();                     // P visible to all warps

        // ---- O += P V : warp rows [g*16,+16) x dh [d*64,+64), all 32 keys
#pragma unroll
        for (int kk = 0; kk < 2; kk++) {
            uint32_t pah[4], pal[4];
            {
                int r = g * 16 + (lane & 15);
                int c = kk * 16 + ((lane >> 4) * 8);
                ldsm_x4(smem_u32(Ph + r * PP + c), pah[0], pah[1], pah[2], pah[3]);
                ldsm_x4(smem_u32(Pl + r * PP + c), pal[0], pal[1], pal[2], pal[3]);
            }
#pragma unroll
            for (int p = 0; p < 4; p++) {
                int r = kk * 16 + (lane & 15);
                int c = d * 64 + p * 16 + ((lane >> 4) * 8);
                uint32_t vh0[2], vh1[2], vl0[2], vl1[2];
                uint32_t t0, t1, t2, t3;
                ldsm_x4_t(smem_u32(Vh + st + r * KVP + c), t0, t1, t2, t3);
                vh0[0] = t0; vh0[1] = t1; vh1[0] = t2; vh1[1] = t3;
                ldsm_x4_t(smem_u32(Vl + st + r * KVP + c), t0, t1, t2, t3);
                vl0[0] = t0; vl0[1] = t1; vl1[0] = t2; vl1[1] = t3;
                mma16816(o[2*p],   pah, vh0);
                mma16816(o[2*p],   pah, vl0);
                mma16816(o[2*p],   pal, vh0);
                mma16816(o[2*p+1], pah, vh1);
                mma16816(o[2*p+1], pah, vl1);
                mma16816(o[2*p+1], pal, vh1);
            }
        }
    }

    // ---- combine l across key-halves, normalize, store z planes
    __syncthreads();                         // last PV done; P region reusable
    lp[0] += __shfl_xor_sync(0xffffffffu, lp[0], 1);
    lp[0] += __shfl_xor_sync(0xffffffffu, lp[0], 2);
    lp[1] += __shfl_xor_sync(0xffffffffu, lp[1], 1);
    lp[1] += __shfl_xor_sync(0xffffffffu, lp[1], 2);

    float* lred = (float*)Ph;                // 64 rows x 2 halves
    if ((lane & 3) == 0) {
        int r0 = g * 16 + (lane >> 2);
        lred[r0 * 2 + d]       = lp[0];
        lred[(r0 + 8) * 2 + d] = lp[1];
    }
    __syncthreads();

#pragma unroll
    for (int rr = 0; rr < 2; rr++) {
        int rl = g * 16 + (lane >> 2) + rr * 8;
        float inv = 1.0f / (lred[rl * 2] + lred[rl * 2 + 1]);
        size_t row = rowBase + q0 + rl;
#pragma unroll
        for (int nt = 0; nt < 8; nt++) {
            int col = colBase + d * 64 + nt * 8 + (lane & 3) * 2;
            float vx = o[nt][2*rr]     * inv;
            float vy = o[nt][2*rr + 1] * inv;
            __nv_bfloat162 hh = __floats2bfloat162_rn(vx, vy);
            float2 f = __bfloat1622float2(hh);
            __nv_bfloat162 ll = __floats2bfloat162_rn(vx - f.x, vy - f.y);
            *(__nv_bfloat162*)(ZH + row * DMODEL + col) = hh;
            *(__nv_bfloat162*)(ZL + row * DMODEL + col) = ll;
        }
    }
}

// ---------------------------------------------------------------------------
extern "C" void kernel_launch(void* const* d_in, const int* in_sizes, int n_in,
                              void* d_out, int out_size)
{
    const float* x     = (const float*)d_in[0];
    const float* W_qkv = (const float*)d_in[1];
    const float* b_qkv = (const float*)d_in[2];
    const float* W_o   = (const float*)d_in[3];
    const float* b_o   = (const float*)d_in[4];
    const float* wq    = (const float*)d_in[5];
    const float* wk    = (const float*)d_in[6];

    float* out   = (float*)d_out;                               // [4096,2048]
    float* k_out = out   + (size_t)MROWS * DMODEL;
    float* v_out = k_out + (size_t)MROWS * DMODEL;

    float* qPtr;
    __nv_bfloat16 *xh, *xl, *Wqh, *Wql, *Woh, *Wol;
    __nv_bfloat16 *qh, *ql, *kh, *kl, *vh, *vl, *zh, *zl;
    cudaGetSymbolAddress((void**)&qPtr, g_q);
    cudaGetSymbolAddress((void**)&xh,  g_xh);  cudaGetSymbolAddress((void**)&xl,  g_xl);
    cudaGetSymbolAddress((void**)&Wqh, g_Wqh); cudaGetSymbolAddress((void**)&Wql, g_Wql);
    cudaGetSymbolAddress((void**)&Woh, g_Woh); cudaGetSymbolAddress((void**)&Wol, g_Wol);
    cudaGetSymbolAddress((void**)&qh,  g_qh);  cudaGetSymbolAddress((void**)&ql,  g_ql);
    cudaGetSymbolAddress((void**)&kh,  g_kh);  cudaGetSymbolAddress((void**)&kl,  g_kl);
    cudaGetSymbolAddress((void**)&vh,  g_vh);  cudaGetSymbolAddress((void**)&vl,  g_vl);
    cudaGetSymbolAddress((void**)&zh,  g_zh);  cudaGetSymbolAddress((void**)&zl,  g_zl);

    // 0) split inputs to bf16 hi/lo planes
    {
        int n4x = MROWS * DMODEL / 4;
        split_kernel<<<(n4x + 255) / 256, 256>>>(x, xh, xl, n4x);
        int n4q = NQKV * DMODEL / 4;
        split_kernel<<<(n4q + 255) / 256, 256>>>(W_qkv, Wqh, Wql, n4q);
        int n4o = DMODEL * DMODEL / 4;
        split_kernel<<<(n4o + 255) / 256, 256>>>(W_o, Woh, Wol, n4o);
    }

    int gemm_smem = 4 * GSTAGES * GTSZ * (int)sizeof(__nv_bfloat16);   // 80 KB
    cudaFuncSetAttribute(gemm_planes, cudaFuncAttributeMaxDynamicSharedMemorySize, gemm_smem);

    // 1) QKV projection
    {
        dim3 grid(NQKV / 128, MROWS / 128);
        gemm_planes<<<grid, 256, gemm_smem>>>(xh, xl, Wqh, Wql, b_qkv,
                                              qPtr, k_out, v_out, vh, vl,
                                              MROWS, NQKV, DMODEL, 1);
    }

    // 2) RMS norm q/k -> bf16 planes
    {
        dim3 grid(MROWS * NHEADS, 2);
        rmsnorm_split<<<grid, DHEAD>>>(qPtr, k_out, qh, ql, kh, kl, wq, wk);
    }

    // 3) Attention -> z planes (8 warps, 2 CTAs/SM, no-rescale softmax)
    {
        int smem = (2 * 64 * 128 + 8 * KVT + 2 * 64 * PP) * (int)sizeof(__nv_bfloat16); // 112640 B
        cudaFuncSetAttribute(attn_tc4, cudaFuncAttributeMaxDynamicSharedMemorySize, smem);
        dim3 grid(SEQ / 64, NHEADS, BATCH);
        attn_tc4<<<grid, 256, smem>>>(qh, ql, kh, kl, vh, vl, zh, zl);
    }

    // 4) Output projection
    {
        dim3 grid(DMODEL / 128, MROWS / 128);
        gemm_planes<<<grid, 256, gemm_smem>>>(zh, zl, Woh, Wol, b_o,
                                              out, nullptr, nullptr, nullptr, nullptr,
                                              MROWS, DMODEL, DMODEL, 0);
    }
}